// round 11
// baseline (speedup 1.0000x reference)
#include <cuda_runtime.h>
#include <cuda_bf16.h>

#define NTAGS 64
#define LOG2E 1.4426950408889634f
#define LN2   0.69314718055994531f

__device__ __forceinline__ float fast_ex2(float x) {
    float r; asm("ex2.approx.ftz.f32 %0, %1;" : "=f"(r) : "f"(x)); return r;
}
__device__ __forceinline__ float fast_lg2(float x) {
    float r; asm("lg2.approx.ftz.f32 %0, %1;" : "=f"(r) : "f"(x)); return r;
}
__device__ __forceinline__ void fma2(unsigned long long& d, unsigned long long a, unsigned long long b) {
    asm("fma.rn.f32x2 %0, %1, %2, %0;" : "+l"(d) : "l"(a), "l"(b));
}
__device__ __forceinline__ unsigned long long add2(unsigned long long a, unsigned long long b) {
    unsigned long long r; asm("add.rn.f32x2 %0, %1, %2;" : "=l"(r) : "l"(a), "l"(b)); return r;
}
__device__ __forceinline__ unsigned long long pack2(float x, float y) {
    unsigned long long r; asm("mov.b64 %0, {%1, %2};" : "=l"(r) : "f"(x), "f"(y)); return r;
}
__device__ __forceinline__ float2 unpack2(unsigned long long v) {
    float2 f; asm("mov.b64 {%0, %1}, %2;" : "=f"(f.x), "=f"(f.y) : "l"(v)); return f;
}

// Batch indices sorted by length DESCENDING.
__device__ int g_perm[8192];

__global__ void sort_len_kernel(const int* __restrict__ lengths, int B) {
    const int K = 1024;
    __shared__ unsigned long long key[K];
    const int tid = threadIdx.x;
    if (B > K) {                       // fallback: identity + pad (still correct)
        for (int i = tid; i < 8192; i += blockDim.x) g_perm[i] = (i < B) ? i : -1;
        return;
    }
    unsigned long long v = (tid < B)
        ? (((unsigned long long)(unsigned)lengths[tid] << 13) | (unsigned)tid)
        : 0ull;                        // pad sinks to the end (real len >= 1)
    key[tid] = v;
    __syncthreads();
    for (int k = 2; k <= K; k <<= 1) {
        for (int j = k >> 1; j > 0; j >>= 1) {
            int l = tid ^ j;
            if (l > tid) {
                unsigned long long a = key[tid], b = key[l];
                bool up = ((tid & k) == 0);          // descending subsequence
                if (up ? (a < b) : (a > b)) { key[tid] = b; key[l] = a; }
            }
            __syncthreads();
        }
    }
    unsigned long long v2 = key[tid];
    g_perm[tid] = (v2 >> 13) ? (int)(v2 & 0x1FFF) : -1;
}

// rank for a warp-pair index wp (0..3) in CTA k of grid G:
//   slot = wp ^ (wp>>1)  (Gray code: 0,1,3,2)
//   slot0 -> rank k        (long,  SMSP 0,1)
//   slot1 -> rank k+G      (long,  SMSP 2,3)
//   slot3 -> rank 4G-1-k   (short, SMSP 0,1)
//   slot2 -> rank 3G-1-k   (short, SMSP 2,3)
__device__ __forceinline__ int pair_rank(int wp, int k, int G) {
    const int slot = wp ^ (wp >> 1);
    switch (slot) {
        case 0:  return k;
        case 1:  return k + G;
        case 2:  return 3 * G - 1 - k;
        default: return 4 * G - 1 - k;
    }
}

// One CTA (256 threads) = 4 batches x {fwd,bwd} = 8 SELF-CONTAINED warps.
// grid = ceil(B/4) -> exactly 1 CTA per SM (no co-residency lottery).
// Every SMSP hosts one long-chain warp + one short-chain warp; the short one
// drains early, so the critical chain runs SOLO (~250 cyc/round) instead of
// 2-warp contended (~380). Per-SMSP total rounds constant across CTAs.
//
// Each warp owns one (batch, direction) chain end-to-end; state exchanged via
// its own smem double buffer + __syncwarp (no cross-warp sync in mainloop).
// Lane l owns tags t0=2l, t1=2l+1; f32x2 packs adjacent j-columns.
//   fwd: P <- diag(f_r) E P ; bwd: A <- f (*) E^T A (extra folded emission
//   divided out at the end). Per-round normalization by q = vec[0] in linear
//   domain; answer = LN2*(m2F + m2B + lg2(dot(F, A))).
__global__ __launch_bounds__(256, 1)
void crf_fwd_kernel(const float* __restrict__ h, const float* __restrict__ trans,
                    const int* __restrict__ lengths, float* __restrict__ out,
                    int B, int T)
{
    const int tid = threadIdx.x;
    const int w   = tid >> 5;
    const int l   = tid & 31;
    const int dir = w & 1;                  // 0 = forward, 1 = backward
    const int t0 = 2 * l;
    const int t1 = 2 * l + 1;

    const int G = gridDim.x;
    const int k = blockIdx.x;
    const int rank = pair_rank(w >> 1, k, G);

    const int bv = (rank < 8192) ? g_perm[rank] : -1;
    const bool valid = (bv >= 0);
    const int b   = valid ? bv : 0;
    const int len = valid ? lengths[b] : 1;
    const int mid = (len + 1) >> 1;
    const int rounds = dir ? (len - mid) : mid;   // exact per-warp trip count

    __shared__ __align__(16) float pbuf[8][2][NTAGS]; // per-warp double buffer
    __shared__ __align__(16) float fin[8][NTAGS];
    __shared__ float fm2[8];

    // E cache: 64 u64 regs, two adjacent j-values per register.
    unsigned long long E0[32], E1[32];
    if (dir == 0) {
        const float4* r0p = reinterpret_cast<const float4*>(trans + t0 * NTAGS);
        const float4* r1p = reinterpret_cast<const float4*>(trans + t1 * NTAGS);
        #pragma unroll
        for (int kk = 0; kk < 16; kk++) {
            float4 a = r0p[kk], c = r1p[kk];
            E0[2 * kk]     = pack2(fast_ex2(a.x * LOG2E), fast_ex2(a.y * LOG2E));
            E0[2 * kk + 1] = pack2(fast_ex2(a.z * LOG2E), fast_ex2(a.w * LOG2E));
            E1[2 * kk]     = pack2(fast_ex2(c.x * LOG2E), fast_ex2(c.y * LOG2E));
            E1[2 * kk + 1] = pack2(fast_ex2(c.z * LOG2E), fast_ex2(c.w * LOG2E));
        }
    } else {
        #pragma unroll
        for (int j2 = 0; j2 < 32; j2++) {
            E0[j2] = pack2(fast_ex2(trans[(2 * j2) * NTAGS + t0] * LOG2E),
                           fast_ex2(trans[(2 * j2 + 1) * NTAGS + t0] * LOG2E));
            E1[j2] = pack2(fast_ex2(trans[(2 * j2) * NTAGS + t1] * LOG2E),
                           fast_ex2(trans[(2 * j2 + 1) * NTAGS + t1] * LOG2E));
        }
    }

    const float* __restrict__ hb = h + (size_t)b * T * NTAGS;

    // initial state
    float px0, px1, m2 = 0.0f, el0 = 0.0f, el1 = 0.0f;
    if (dir == 0) {
        px0 = (t0 == NTAGS - 2) ? 1.0f : 0.0f;   // START_TAG = 62 (even)
        px1 = 0.0f;
    } else {
        float u0 = fast_ex2(trans[(NTAGS - 1) * NTAGS + t0] * LOG2E);
        float u1 = fast_ex2(trans[(NTAGS - 1) * NTAGS + t1] * LOG2E);
        float2 ei = *reinterpret_cast<const float2*>(hb + (size_t)(len - 1) * NTAGS + t0);
        el0 = ei.x; el1 = ei.y;
        px0 = u0 * fast_ex2(el0 * LOG2E);
        px1 = u1 * fast_ex2(el1 * LOG2E);
    }
    *reinterpret_cast<float2*>(&pbuf[w][0][t0]) = make_float2(px0, px1);
    __syncwarp();

    // emission pipeline (2 deep): index at round r = fwd: r ; bwd: max(len-2-r,0)
    const int Tm1 = T - 1;
    const int ia = dir ? max(len - 2, 0) : 0;
    const int ib = dir ? max(len - 3, 0) : min(1, Tm1);
    float2 ea = *reinterpret_cast<const float2*>(hb + (size_t)ia * NTAGS + t0);
    float2 eb = *reinterpret_cast<const float2*>(hb + (size_t)ib * NTAGS + t0);

    int buf = 0;
    for (int r = 0; r < rounds; r++) {
        const ulonglong2* Pv = reinterpret_cast<const ulonglong2*>(&pbuf[w][buf][0]);

        ulonglong2 v0 = Pv[0];
        float2 qq = unpack2(v0.x);
        float q = ((dir == 0) & (r == 0)) ? 1.0f : qq.x;   // fwd round 0: P[0]==0

        unsigned long long a00 = 0, a01 = 0, a10 = 0, a11 = 0;
        fma2(a00, E0[0], v0.x); fma2(a10, E1[0], v0.x);
        fma2(a01, E0[1], v0.y); fma2(a11, E1[1], v0.y);

        // normalizer + emission factors on MUFU, overlapped with the dot
        float l2q = fast_lg2(q);
        float r0f = fast_ex2(fmaf(ea.x, LOG2E, -l2q));
        float r1f = fast_ex2(fmaf(ea.y, LOG2E, -l2q));

        #pragma unroll
        for (int kk = 1; kk < 16; kk++) {
            ulonglong2 v = Pv[kk];
            fma2(a00, E0[2 * kk],     v.x); fma2(a10, E1[2 * kk],     v.x);
            fma2(a01, E0[2 * kk + 1], v.y); fma2(a11, E1[2 * kk + 1], v.y);
        }

        // prefetch emissions for round r+2 (clamped, memory-safe)
        const int ni = dir ? max(len - 4 - r, 0) : min(r + 2, Tm1);
        float2 ec = *reinterpret_cast<const float2*>(hb + (size_t)ni * NTAGS + t0);

        float2 s0 = unpack2(add2(a00, a01));
        float2 s1 = unpack2(add2(a10, a11));
        float S0 = s0.x + s0.y;
        float S1 = s1.x + s1.y;

        px0 = S0 * r0f;
        px1 = S1 * r1f;
        m2 += l2q;
        el0 = ea.x; el1 = ea.y;        // most recent folded emission (bwd use)

        *reinterpret_cast<float2*>(&pbuf[w][buf ^ 1][t0]) = make_float2(px0, px1);
        __syncwarp();

        ea = eb; eb = ec;
        buf ^= 1;
    }

    // backward state carries one extra folded emission: divide it out
    float c0 = dir ? fast_ex2(-el0 * LOG2E) : 1.0f;
    float c1 = dir ? fast_ex2(-el1 * LOG2E) : 1.0f;
    *reinterpret_cast<float2*>(&fin[w][t0]) = make_float2(px0 * c0, px1 * c1);
    if (l == 0) fm2[w] = m2;
    __syncthreads();

    // Epilogue: warp p (p<4) reduces the batch of warp-pair p (warps 2p, 2p+1).
    if (tid < 128) {
        const int p    = tid >> 5;
        const int lane = tid & 31;
        const int fw   = p * 2;            // fwd warp of warp-pair p
        float sx = fin[fw][lane]      * fin[fw + 1][lane]
                 + fin[fw][lane + 32] * fin[fw + 1][lane + 32];
        #pragma unroll
        for (int o = 16; o > 0; o >>= 1)
            sx += __shfl_xor_sync(0xffffffffu, sx, o);
        if (lane == 0) {
            const int rk  = pair_rank(p, k, G);
            const int obv = (rk < 8192) ? g_perm[rk] : -1;
            if (obv >= 0)
                out[obv] = LN2 * (fm2[fw] + fm2[fw + 1] + fast_lg2(sx));
        }
    }
}

extern "C" void kernel_launch(void* const* d_in, const int* in_sizes, int n_in,
                              void* d_out, int out_size)
{
    const float* h       = (const float*)d_in[0];   // [B, T, N] f32
    const float* trans   = (const float*)d_in[1];   // [N, N]    f32
    const int*   lengths = (const int*)d_in[2];     // [B]       i32
    float*       out     = (float*)d_out;           // [B]       f32

    const int B = in_sizes[2];
    const int T = in_sizes[0] / (B * NTAGS);

    sort_len_kernel<<<1, 1024>>>(lengths, B);

    const int nblk = (B + 3) / 4;
    crf_fwd_kernel<<<nblk, 256>>>(h, trans, lengths, out, B, T);
}

// round 12
// speedup vs baseline: 1.1366x; 1.1366x over previous
#include <cuda_runtime.h>
#include <cuda_bf16.h>

#define NTAGS 64
#define LOG2E 1.4426950408889634f
#define LN2   0.69314718055994531f

__device__ __forceinline__ float fast_ex2(float x) {
    float r; asm("ex2.approx.ftz.f32 %0, %1;" : "=f"(r) : "f"(x)); return r;
}
__device__ __forceinline__ float fast_lg2(float x) {
    float r; asm("lg2.approx.ftz.f32 %0, %1;" : "=f"(r) : "f"(x)); return r;
}
__device__ __forceinline__ void fma2(unsigned long long& d, unsigned long long a, unsigned long long b) {
    asm("fma.rn.f32x2 %0, %1, %2, %0;" : "+l"(d) : "l"(a), "l"(b));
}
__device__ __forceinline__ unsigned long long add2(unsigned long long a, unsigned long long b) {
    unsigned long long r; asm("add.rn.f32x2 %0, %1, %2;" : "=l"(r) : "l"(a), "l"(b)); return r;
}
__device__ __forceinline__ unsigned long long pack2(float x, float y) {
    unsigned long long r; asm("mov.b64 %0, {%1, %2};" : "=l"(r) : "f"(x), "f"(y)); return r;
}
__device__ __forceinline__ float2 unpack2(unsigned long long v) {
    float2 f; asm("mov.b64 {%0, %1}, %2;" : "=f"(f.x), "=f"(f.y) : "l"(v)); return f;
}

#define CHAIN_BAR(id) asm volatile("bar.sync %0, 64;" :: "r"(id) : "memory")

// Batch indices sorted by length DESCENDING.
__device__ int g_perm[8192];

__global__ void sort_len_kernel(const int* __restrict__ lengths, int B) {
    const int K = 1024;
    __shared__ unsigned long long key[K];
    const int tid = threadIdx.x;
    if (B > K) {
        for (int i = tid; i < 8192; i += blockDim.x) g_perm[i] = (i < B) ? i : -1;
        return;
    }
    unsigned long long v = (tid < B)
        ? (((unsigned long long)(unsigned)lengths[tid] << 13) | (unsigned)tid)
        : 0ull;
    key[tid] = v;
    __syncthreads();
    for (int k = 2; k <= K; k <<= 1) {
        for (int j = k >> 1; j > 0; j >>= 1) {
            int l = tid ^ j;
            if (l > tid) {
                unsigned long long a = key[tid], b = key[l];
                bool up = ((tid & k) == 0);
                if (up ? (a < b) : (a > b)) { key[tid] = b; key[l] = a; }
            }
            __syncthreads();
        }
    }
    unsigned long long v2 = key[tid];
    g_perm[tid] = (v2 >> 13) ? (int)(v2 & 0x1FFF) : -1;
}

// rank for batch slot q (0..3) in CTA k of grid G (Gray code slot map 0,1,3,2):
//   slot0 -> rank k (long)   slot1 -> rank k+G (long)
//   slot2 -> rank 3G-1-k     slot3 -> rank 4G-1-k (short complements)
__device__ __forceinline__ int pair_rank(int q, int k, int G) {
    const int slot = q ^ (q >> 1);
    switch (slot) {
        case 0:  return k;
        case 1:  return k + G;
        case 2:  return 3 * G - 1 - k;
        default: return 4 * G - 1 - k;
    }
}

// One CTA (512 threads) = 4 batches x {fwd,bwd} = 8 chains, EACH chain = 2 warps
// splitting the 64-term dot in half (32 fma2/warp instead of 64 -> half the
// per-round issue). grid = ceil(B/4) -> 1 CTA/SM.
//   chain c: batch q=c>>1, dir=c&1; warps 2c (j in [0,32)) and 2c+1 (j in [32,64)).
//   -> fwd halves land on SMSP 0,1 and bwd halves on SMSP 2,3 for every batch;
//      each SMSP mixes 2 long + 2 short chains (shorts drain early).
// Per round: each warp does its half-dot, stores a packed partial, one 64-thread
// named barrier, then BOTH warps combine + scale and store the identical P'
// (identical-value race is benign; __syncwarp orders each warp's own reads).
//
// fwd: P <- diag(f_r) E P ; bwd: A <- f (*) E^T A (extra folded emission divided
// out at the end). Per-round normalization by q = P[0] in linear domain;
// answer = LN2*(m2F + m2B + lg2(dot(F, A))).
__global__ __launch_bounds__(512, 1)
void crf_fwd_kernel(const float* __restrict__ h, const float* __restrict__ trans,
                    const int* __restrict__ lengths, float* __restrict__ out,
                    int B, int T)
{
    const int tid  = threadIdx.x;
    const int w    = tid >> 5;
    const int l    = tid & 31;
    const int c    = w >> 1;            // chain 0..7
    const int half = w & 1;             // j-half of the dot
    const int qb   = c >> 1;            // batch slot 0..3
    const int dir  = c & 1;             // 0 = forward, 1 = backward
    const int barid = c + 1;
    const int t0 = 2 * l, t1 = 2 * l + 1;
    const int j0 = half * 32;

    const int G = gridDim.x;
    const int kb = blockIdx.x;
    const int rank = pair_rank(qb, kb, G);
    const int bv = (rank < 8192) ? g_perm[rank] : -1;
    const int b   = (bv >= 0) ? bv : 0;
    const int len = (bv >= 0) ? lengths[b] : 1;
    const int mid = (len + 1) >> 1;
    const int rounds = dir ? (len - mid) : mid;

    __shared__ __align__(16) float pfull[8][NTAGS];                 // chain state
    __shared__ __align__(16) unsigned long long part[8][2][NTAGS];  // [c][buf][2l+half]
    __shared__ __align__(16) float fin[8][NTAGS];
    __shared__ float fm2[8];

    // E cache: this warp's j-half only (32 u64 = 64 regs).
    // fwd: rows t0,t1 of E ; bwd: columns t0,t1 of E (i.e. rows of E^T).
    unsigned long long E0[16], E1[16];
    if (dir == 0) {
        #pragma unroll
        for (int i = 0; i < 8; i++) {
            float4 a = *reinterpret_cast<const float4*>(trans + t0 * NTAGS + j0 + 4 * i);
            float4 d = *reinterpret_cast<const float4*>(trans + t1 * NTAGS + j0 + 4 * i);
            E0[2 * i]     = pack2(fast_ex2(a.x * LOG2E), fast_ex2(a.y * LOG2E));
            E0[2 * i + 1] = pack2(fast_ex2(a.z * LOG2E), fast_ex2(a.w * LOG2E));
            E1[2 * i]     = pack2(fast_ex2(d.x * LOG2E), fast_ex2(d.y * LOG2E));
            E1[2 * i + 1] = pack2(fast_ex2(d.z * LOG2E), fast_ex2(d.w * LOG2E));
        }
    } else {
        #pragma unroll
        for (int i = 0; i < 16; i++) {
            int j = j0 + 2 * i;
            E0[i] = pack2(fast_ex2(trans[j * NTAGS + t0] * LOG2E),
                          fast_ex2(trans[(j + 1) * NTAGS + t0] * LOG2E));
            E1[i] = pack2(fast_ex2(trans[j * NTAGS + t1] * LOG2E),
                          fast_ex2(trans[(j + 1) * NTAGS + t1] * LOG2E));
        }
    }

    const float* __restrict__ hb = h + (size_t)b * T * NTAGS;

    // initial state (identical in both half-warps)
    float px0, px1, m2 = 0.0f, el0 = 0.0f, el1 = 0.0f;
    if (dir == 0) {
        px0 = (t0 == NTAGS - 2) ? 1.0f : 0.0f;   // START_TAG = 62 (even)
        px1 = 0.0f;
    } else {
        float u0 = fast_ex2(trans[(NTAGS - 1) * NTAGS + t0] * LOG2E);
        float u1 = fast_ex2(trans[(NTAGS - 1) * NTAGS + t1] * LOG2E);
        float2 ei = *reinterpret_cast<const float2*>(hb + (size_t)(len - 1) * NTAGS + t0);
        el0 = ei.x; el1 = ei.y;
        px0 = u0 * fast_ex2(el0 * LOG2E);
        px1 = u1 * fast_ex2(el1 * LOG2E);
    }
    *reinterpret_cast<float2*>(&pfull[c][t0]) = make_float2(px0, px1);
    CHAIN_BAR(barid);

    // emission pipeline (2 deep): index at round r = fwd: r ; bwd: max(len-2-r,0)
    const int Tm1 = T - 1;
    const int ia = dir ? max(len - 2, 0) : 0;
    const int ib = dir ? max(len - 3, 0) : min(1, Tm1);
    float2 ea = *reinterpret_cast<const float2*>(hb + (size_t)ia * NTAGS + t0);
    float2 eb = *reinterpret_cast<const float2*>(hb + (size_t)ib * NTAGS + t0);

    int buf = 0;
    for (int r = 0; r < rounds; r++) {
        // normalizer q = P[0] (broadcast LDS; self-written last round)
        float qv = pfull[c][0];
        float qq = ((dir == 0) & (r == 0)) ? 1.0f : qv;

        const ulonglong2* Pv = reinterpret_cast<const ulonglong2*>(&pfull[c][j0]);
        ulonglong2 v0 = Pv[0];

        unsigned long long a00 = 0, a01 = 0, a10 = 0, a11 = 0;
        fma2(a00, E0[0], v0.x); fma2(a10, E1[0], v0.x);
        fma2(a01, E0[1], v0.y); fma2(a11, E1[1], v0.y);

        // normalizer + emission factors on MUFU, overlapped with the half-dot
        float l2q = fast_lg2(qq);
        float r0f = fast_ex2(fmaf(ea.x, LOG2E, -l2q));
        float r1f = fast_ex2(fmaf(ea.y, LOG2E, -l2q));

        #pragma unroll
        for (int i = 1; i < 8; i++) {
            ulonglong2 v = Pv[i];
            fma2(a00, E0[2 * i],     v.x); fma2(a10, E1[2 * i],     v.x);
            fma2(a01, E0[2 * i + 1], v.y); fma2(a11, E1[2 * i + 1], v.y);
        }

        // prefetch emissions for round r+2 (clamped, memory-safe)
        const int ni = dir ? max(len - 4 - r, 0) : min(r + 2, Tm1);
        float2 ec = *reinterpret_cast<const float2*>(hb + (size_t)ni * NTAGS + t0);

        // pack this half's partial (S_t0, S_t1)
        float2 sA = unpack2(add2(a00, a01));
        float2 sB = unpack2(add2(a10, a11));
        part[c][buf][2 * l + half] = pack2(sA.x + sA.y, sB.x + sB.y);
        CHAIN_BAR(barid);

        // combine halves, scale, store P' (both warps write identical values)
        ulonglong2 pp = *reinterpret_cast<const ulonglong2*>(&part[c][buf][2 * l]);
        float2 S = unpack2(add2(pp.x, pp.y));
        px0 = S.x * r0f;
        px1 = S.y * r1f;
        m2 += l2q;
        el0 = ea.x; el1 = ea.y;

        *reinterpret_cast<float2*>(&pfull[c][t0]) = make_float2(px0, px1);
        __syncwarp();

        ea = eb; eb = ec;
        buf ^= 1;
    }

    // backward state carries one extra folded emission: divide it out
    float c0 = dir ? fast_ex2(-el0 * LOG2E) : 1.0f;
    float c1 = dir ? fast_ex2(-el1 * LOG2E) : 1.0f;
    if (half == 0) {
        *reinterpret_cast<float2*>(&fin[c][t0]) = make_float2(px0 * c0, px1 * c1);
        if (l == 0) fm2[c] = m2;
    }
    __syncthreads();

    // Epilogue: warp p (p<4) reduces batch slot p.
    if (tid < 128) {
        const int p    = tid >> 5;
        const int lane = tid & 31;
        const int fc   = p * 2;            // fwd chain of batch p; bwd = fc+1
        float sx = fin[fc][lane]      * fin[fc + 1][lane]
                 + fin[fc][lane + 32] * fin[fc + 1][lane + 32];
        #pragma unroll
        for (int o = 16; o > 0; o >>= 1)
            sx += __shfl_xor_sync(0xffffffffu, sx, o);
        if (lane == 0) {
            const int rk  = pair_rank(p, kb, G);
            const int obv = (rk < 8192) ? g_perm[rk] : -1;
            if (obv >= 0)
                out[obv] = LN2 * (fm2[fc] + fm2[fc + 1] + fast_lg2(sx));
        }
    }
}

extern "C" void kernel_launch(void* const* d_in, const int* in_sizes, int n_in,
                              void* d_out, int out_size)
{
    const float* h       = (const float*)d_in[0];   // [B, T, N] f32
    const float* trans   = (const float*)d_in[1];   // [N, N]    f32
    const int*   lengths = (const int*)d_in[2];     // [B]       i32
    float*       out     = (float*)d_out;           // [B]       f32

    const int B = in_sizes[2];
    const int T = in_sizes[0] / (B * NTAGS);

    sort_len_kernel<<<1, 1024>>>(lengths, B);

    const int nblk = (B + 3) / 4;
    crf_fwd_kernel<<<nblk, 512>>>(h, trans, lengths, out, B, T);
}